// round 7
// baseline (speedup 1.0000x reference)
#include <cuda_runtime.h>
#include <cstddef>

// ---------------- device scratch (zero-init; consume-and-clear / last-warp reset keep it clean) ----
#define MAX_N 262144
__device__ float    g_v[128];           // proj_w @ w_st
__device__ float    g_u[64];            // w_his2 @ w_st
__device__ float    g_U[16];            // user_out[b] + b_u + b_st
__device__ float    g_c;                // proj_b · w_st
__device__ float    g_bh2;              // b_his2 · w_st
__device__ float    g_delta[1 << 20];   // per-(b,n) scattered correction
__device__ unsigned g_flag[MAX_N];      // per-n batch bitmask
__device__ int      g_done_prep;        // prep warps finished (17)
__device__ int      g_done_corr;        // corr warps finished (2*BK)
__device__ int      g_readers;          // end-of-kernel handshake

#define GRID_BLOCKS 148
#define PREP_WARPS  17

__device__ __forceinline__ float warp_sum(float p) {
    #pragma unroll
    for (int off = 16; off; off >>= 1)
        p += __shfl_xor_sync(0xffffffffu, p, off);
    return p;
}

// 8 independent row-dot reductions in 9 shuffles. Input: a[i] = per-lane partial of row i.
// Output: every lane holds the full sum of row = ((lane>>4)&1)*4 + ((lane>>3)&1)*2 + ((lane>>2)&1).
__device__ __forceinline__ float reduce8(const float a_in[8], int lane) {
    float b[4];
    bool h1 = lane & 16;
    #pragma unroll
    for (int k = 0; k < 4; ++k) {
        float send = h1 ? a_in[k]     : a_in[k + 4];
        float keep = h1 ? a_in[k + 4] : a_in[k];
        b[k] = keep + __shfl_xor_sync(0xffffffffu, send, 16);
    }
    float c[2];
    bool h2 = lane & 8;
    #pragma unroll
    for (int k = 0; k < 2; ++k) {
        float send = h2 ? b[k]     : b[k + 2];
        float keep = h2 ? b[k + 2] : b[k];
        c[k] = keep + __shfl_xor_sync(0xffffffffu, send, 8);
    }
    bool h3 = lane & 4;
    float send = h3 ? c[0] : c[1];
    float keep = h3 ? c[1] : c[0];
    float d = keep + __shfl_xor_sync(0xffffffffu, send, 4);
    d += __shfl_xor_sync(0xffffffffu, d, 2);
    d += __shfl_xor_sync(0xffffffffu, d, 1);
    return d;
}

__device__ __forceinline__ void spin_ge(int* ctr, int target, int lane) {
    if (lane == 0) {
        while (*(volatile int*)ctr < target) __nanosleep(64);
    }
    __syncwarp();
    __threadfence();   // acquire: order subsequent reads after the observed counter
}

__device__ __forceinline__ void signal(int* ctr, int lane) {
    __threadfence();   // release: my writes visible before the count
    __syncwarp();
    if (lane == 0) atomicAdd(ctr, 1);
}

__global__ __launch_bounds__(256)
void fused_kernel(const float* __restrict__ set_table,
                  const float* __restrict__ station_embedding,
                  const float* __restrict__ raw_field_embed,
                  const float* __restrict__ alpha,
                  const float* __restrict__ w_st,
                  const float* __restrict__ w_his1,
                  const float* __restrict__ b_his1,
                  const float* __restrict__ w_his2,
                  const float* __restrict__ b_his2,
                  const float* __restrict__ proj_w,
                  const float* __restrict__ proj_b,
                  const float* __restrict__ w_u,
                  const float* __restrict__ b_u,
                  const float* __restrict__ b_st,
                  const float* __restrict__ user_embedding,
                  const float* __restrict__ user_emb_table,
                  const float* __restrict__ theta,
                  const int* __restrict__ user_id,
                  const int* __restrict__ his_nodes,
                  const int* __restrict__ now_nodes,
                  float* __restrict__ out,
                  int Bn, int N, int K, int BK)
{
    __shared__ float xs[8][128];      // per-warp x staging for his-MLP
    int tid  = threadIdx.x;
    int lane = tid & 31, warp = tid >> 5;
    int W    = blockIdx.x * 8 + warp;
    int TW   = gridDim.x * 8;
    int roleTotal = PREP_WARPS + 2 * BK;

    // ===================== ROLE PHASE =====================
    if (W < 16) {
        // prep: g_v rows [W*8, W*8+8), warps 0..7 also g_u rows
        float4 wv = reinterpret_cast<const float4*>(w_st)[lane];
        {
            int r0 = W * 8;
            float a[8];
            #pragma unroll
            for (int i = 0; i < 8; ++i) {
                float4 r = reinterpret_cast<const float4*>(proj_w + (r0 + i) * 128)[lane];
                a[i] = r.x * wv.x + r.y * wv.y + r.z * wv.z + r.w * wv.w;
            }
            float d = reduce8(a, lane);
            int row = ((lane >> 4) & 1) * 4 + ((lane >> 3) & 1) * 2 + ((lane >> 2) & 1);
            if ((lane & 3) == 0) g_v[r0 + row] = d;
        }
        if (W < 8) {
            int r0 = W * 8;
            float a[8];
            #pragma unroll
            for (int i = 0; i < 8; ++i) {
                float4 r = reinterpret_cast<const float4*>(w_his2 + (r0 + i) * 128)[lane];
                a[i] = r.x * wv.x + r.y * wv.y + r.z * wv.z + r.w * wv.w;
            }
            float d = reduce8(a, lane);
            int row = ((lane >> 4) & 1) * 4 + ((lane >> 3) & 1) * 2 + ((lane >> 2) & 1);
            if ((lane & 3) == 0) g_u[r0 + row] = d;
        }
        signal(&g_done_prep, lane);
    } else if (W == 16) {
        // prep: g_U (4 lanes per b), g_c, g_bh2
        int b = lane >> 2, q = lane & 3;
        if (b < Bn) {
            int uid = user_id[b];
            float th = theta[uid];
            float p = 0.f;
            const float4* ue = reinterpret_cast<const float4*>(user_embedding + b * 128);
            const float4* ut = reinterpret_cast<const float4*>(user_emb_table + (size_t)uid * 128);
            const float4* wu = reinterpret_cast<const float4*>(w_u);
            #pragma unroll
            for (int t = 0; t < 8; ++t) {
                int idx = q * 8 + t;
                float4 e = ue[idx], s = ut[idx], w = wu[idx];
                p += ((1.f - th) * e.x + th * s.x) * w.x
                   + ((1.f - th) * e.y + th * s.y) * w.y
                   + ((1.f - th) * e.z + th * s.z) * w.z
                   + ((1.f - th) * e.w + th * s.w) * w.w;
            }
            p += __shfl_xor_sync(0xffffffffu, p, 1);
            p += __shfl_xor_sync(0xffffffffu, p, 2);
            if (q == 0) g_U[b] = p + b_u[0] + b_st[0];
        }
        float4 wv = reinterpret_cast<const float4*>(w_st)[lane];
        {
            float4 pb = reinterpret_cast<const float4*>(proj_b)[lane];
            float p = warp_sum(pb.x * wv.x + pb.y * wv.y + pb.z * wv.z + pb.w * wv.w);
            if (lane == 0) g_c = p;
        }
        {
            float4 bh = reinterpret_cast<const float4*>(b_his2)[lane];
            float p = warp_sum(bh.x * wv.x + bh.y * wv.y + bh.z * wv.z + bh.w * wv.w);
            if (lane == 0) g_bh2 = p;
        }
        signal(&g_done_prep, lane);
    } else if (W < PREP_WARPS + BK) {
        // his MLP entry
        int e = W - PREP_WARPS;
        int n = his_nodes[e], b = e / K;
        float4 xv = reinterpret_cast<const float4*>(raw_field_embed + (size_t)n * 128)[lane];
        reinterpret_cast<float4*>(&xs[warp][0])[lane] = xv;
        __syncwarp();
        float a0 = b_his1[lane], a1 = b_his1[lane + 32];
        const float* xp = &xs[warp][0];
        #pragma unroll 4
        for (int d = 0; d < 128; ++d) {
            float x = xp[d];
            a0 += x * w_his1[d * 64 + lane];
            a1 += x * w_his1[d * 64 + lane + 32];
        }
        float l0 = a0 > 0.f ? a0 : 0.01f * a0;
        float l1 = a1 > 0.f ? a1 : 0.01f * a1;
        spin_ge(&g_done_prep, PREP_WARPS, lane);   // need g_u / g_bh2
        float val = warp_sum(l0 * g_u[lane] + l1 * g_u[lane + 32]);
        if (lane == 0) {
            atomicAdd(&g_delta[(size_t)b * N + n], alpha[n] * (val + g_bh2));
            atomicOr(&g_flag[n], 1u << b);
        }
        signal(&g_done_corr, lane);
    } else if (W < roleTotal) {
        // now dot entry
        int e = W - PREP_WARPS - BK;
        int n = now_nodes[e], b = e / K;
        float4 w4 = reinterpret_cast<const float4*>(w_st)[lane];
        float4 r  = reinterpret_cast<const float4*>(station_embedding + (size_t)n * 128)[lane];
        float p = warp_sum(r.x * w4.x + r.y * w4.y + r.z * w4.z + r.w * w4.w);
        if (lane == 0) {
            atomicAdd(&g_delta[(size_t)b * N + n], alpha[n] * p);
            atomicOr(&g_flag[n], 1u << b);
        }
        signal(&g_done_corr, lane);
    }

    // ===================== SWEEP PHASE (all warps) =====================
    int ngroups = (N + 7) >> 3;
    // remap so pure-sweep warps take the larger shares; role warps take the tail
    int gw = (W + (TW - roleTotal)) % TW;
    int gid = gw;

    if (gid < ngroups) {
        // issue first group's row loads BEFORE waiting (overlap prefetch with role work)
        float4 cur[8];
        {
            int n0 = gid * 8;
            #pragma unroll
            for (int i = 0; i < 8; ++i) {
                int n = n0 + i;
                cur[i] = (n < N)
                       ? reinterpret_cast<const float4*>(set_table + (size_t)n * 128)[lane]
                       : make_float4(0.f, 0.f, 0.f, 0.f);
            }
        }
        spin_ge(&g_done_prep, PREP_WARPS, lane);
        spin_ge(&g_done_corr, 2 * BK, lane);

        float4 v4  = reinterpret_cast<const float4*>(g_v)[lane];
        float cval = g_c;
        float Uv   = g_U[lane & 7];
        int   row  = ((lane >> 4) & 1) * 4 + ((lane >> 3) & 1) * 2 + ((lane >> 2) & 1);

        unsigned flcur = 0;
        {
            int nf = gid * 8 + lane;
            if (lane < 8 && nf < N) flcur = g_flag[nf];
        }

        for (;;) {
            int gn = gid + TW;
            bool has = gn < ngroups;
            float4 nxt[8];
            unsigned flnxt = 0;
            if (has) {
                int n0 = gn * 8;
                #pragma unroll
                for (int i = 0; i < 8; ++i) {
                    int n = n0 + i;
                    nxt[i] = (n < N)
                           ? reinterpret_cast<const float4*>(set_table + (size_t)n * 128)[lane]
                           : make_float4(0.f, 0.f, 0.f, 0.f);
                }
                int nf = n0 + lane;
                if (lane < 8 && nf < N) flnxt = g_flag[nf];
            }

            // reduce current 8 rows (9 shuffles)
            float a[8];
            #pragma unroll
            for (int i = 0; i < 8; ++i)
                a[i] = cur[i].x * v4.x + cur[i].y * v4.y + cur[i].z * v4.z + cur[i].w * v4.w;
            float s = reduce8(a, lane) + cval;

            int n = gid * 8 + row;
            unsigned f = __shfl_sync(0xffffffffu, flcur, row);

            // writes: each lane covers 2 batch rows for its node
            #pragma unroll
            for (int t = 0; t < 2; ++t) {
                int bb = (lane & 3) + t * 4;
                float Ub = __shfl_sync(0xffffffffu, Uv, bb);
                if (bb < Bn && n < N) {
                    float val = s + Ub;
                    if ((f >> bb) & 1u) {
                        val = (1.f - alpha[n]) * s + Ub + g_delta[(size_t)bb * N + n];
                        g_delta[(size_t)bb * N + n] = 0.f;   // restore zero for next replay
                    }
                    out[(size_t)bb * N + n] = val;
                }
            }
            if ((lane & 3) == 0 && n < N && f) g_flag[n] = 0u;  // restore zero

            if (!has) break;
            gid = gn;
            #pragma unroll
            for (int i = 0; i < 8; ++i) cur[i] = nxt[i];
            flcur = flnxt;
        }
    }

    // ===================== END HANDSHAKE: last warp resets counters =====================
    __syncwarp();
    if (lane == 0) {
        __threadfence();
        int old = atomicAdd(&g_readers, 1);
        if (old == TW - 1) {
            g_done_prep = 0;
            g_done_corr = 0;
            __threadfence();
            g_readers = 0;
        }
    }
}

// ---------------- host launch ----------------
extern "C" void kernel_launch(void* const* d_in, const int* in_sizes, int n_in,
                              void* d_out, int out_size)
{
    int iUE, iSE, iRFE, iHIS, iNOW, iUID, iUET, iSET, iPW, iPB, iTH, iAL,
        iW1, iB1, iW2, iB2, iWST, iBST, iWU, iBU;
    if (in_sizes[3] < 100000) {
        iUE=0; iSE=1; iRFE=2; iHIS=3; iNOW=4; iUID=5; iUET=6; iSET=7; iPW=8; iPB=9;
        iTH=10; iAL=11; iW1=12; iB1=13; iW2=14; iB2=15; iWST=16; iBST=17; iWU=18; iBU=19;
    } else {
        iUE=0; iSE=1; iRFE=2; iUET=3; iSET=4; iPW=5; iPB=6; iTH=7; iAL=8; iW1=9;
        iB1=10; iW2=11; iB2=12; iWST=13; iBST=14; iWU=15; iBU=16; iHIS=17; iNOW=18; iUID=19;
    }

    const float* user_embedding    = (const float*)d_in[iUE];
    const float* station_embedding = (const float*)d_in[iSE];
    const float* raw_field_embed   = (const float*)d_in[iRFE];
    const float* user_emb_table    = (const float*)d_in[iUET];
    const float* station_emb_table = (const float*)d_in[iSET];
    const float* proj_w            = (const float*)d_in[iPW];
    const float* proj_b            = (const float*)d_in[iPB];
    const float* theta             = (const float*)d_in[iTH];
    const float* alpha             = (const float*)d_in[iAL];
    const float* w_his1            = (const float*)d_in[iW1];
    const float* b_his1            = (const float*)d_in[iB1];
    const float* w_his2            = (const float*)d_in[iW2];
    const float* b_his2            = (const float*)d_in[iB2];
    const float* w_st              = (const float*)d_in[iWST];
    const float* b_st              = (const float*)d_in[iBST];
    const float* w_u               = (const float*)d_in[iWU];
    const float* b_u               = (const float*)d_in[iBU];
    const int*   his_nodes         = (const int*)d_in[iHIS];
    const int*   now_nodes         = (const int*)d_in[iNOW];
    const int*   user_id           = (const int*)d_in[iUID];

    int B  = in_sizes[iUE] / 128;     // 8
    int N  = in_sizes[iAL];           // 60082
    int BK = in_sizes[iHIS];          // 256
    int K  = BK / B;                  // 32

    float* out = (float*)d_out;
    (void)out_size; (void)n_in;

    fused_kernel<<<GRID_BLOCKS, 256>>>(
        station_emb_table, station_embedding, raw_field_embed, alpha,
        w_st, w_his1, b_his1, w_his2, b_his2, proj_w, proj_b,
        w_u, b_u, b_st, user_embedding, user_emb_table, theta, user_id,
        his_nodes, now_nodes, out, B, N, K, BK);
}

// round 8
// speedup vs baseline: 2.4169x; 2.4169x over previous
#include <cuda_runtime.h>
#include <cstddef>

// ---------------- device scratch (zero-initialized; consume-and-clear keeps it zeroed) ----------------
#define MAX_N 262144
__device__ float    g_v[128];           // proj_w @ w_st
__device__ float    g_U[16];            // user_out[b] + b_u + b_st
__device__ float    g_c;                // proj_b · w_st
__device__ float    g_delta[1 << 20];   // per-(b,n) scattered correction
__device__ unsigned g_flag[MAX_N];      // per-n batch bitmask

__device__ __forceinline__ float warp_sum(float p) {
    #pragma unroll
    for (int off = 16; off; off >>= 1)
        p += __shfl_xor_sync(0xffffffffu, p, off);
    return p;
}

// 8 independent 32-lane reductions in 9 shuffles. a[i] = per-lane partial of row i.
// Result: every lane holds sum of row = ((lane>>4)&1)*4 + ((lane>>3)&1)*2 + ((lane>>2)&1).
__device__ __forceinline__ float reduce8(const float a_in[8], int lane) {
    float b[4];
    bool h1 = lane & 16;
    #pragma unroll
    for (int k = 0; k < 4; ++k) {
        float send = h1 ? a_in[k]     : a_in[k + 4];
        float keep = h1 ? a_in[k + 4] : a_in[k];
        b[k] = keep + __shfl_xor_sync(0xffffffffu, send, 16);
    }
    float c[2];
    bool h2 = lane & 8;
    #pragma unroll
    for (int k = 0; k < 2; ++k) {
        float send = h2 ? b[k]     : b[k + 2];
        float keep = h2 ? b[k + 2] : b[k];
        c[k] = keep + __shfl_xor_sync(0xffffffffu, send, 8);
    }
    bool h3 = lane & 4;
    float send = h3 ? c[0] : c[1];
    float keep = h3 ? c[1] : c[0];
    float d = keep + __shfl_xor_sync(0xffffffffu, send, 4);
    d += __shfl_xor_sync(0xffffffffu, d, 2);
    d += __shfl_xor_sync(0xffffffffu, d, 1);
    return d;
}

// ---------------- K1: latency-optimized prep + corrections ----------------
// blocks [0, hisBlocks): 16 his entries each, 2 per warp, one-round weight staging
// blocks [hisBlocks, hisBlocks+nowBlocks): 32 now entries each, prefetched
// last block: g_v / g_U / g_c (deep-batched)
__global__ __launch_bounds__(256)
void k1_kernel(const int* __restrict__ now_nodes,
               const int* __restrict__ his_nodes,
               const float* __restrict__ alpha,
               const float* __restrict__ station_embedding,
               const float* __restrict__ raw_field_embed,
               const float* __restrict__ w_st,
               const float* __restrict__ w_his1,
               const float* __restrict__ b_his1,
               const float* __restrict__ w_his2,
               const float* __restrict__ b_his2,
               const float* __restrict__ proj_w,
               const float* __restrict__ proj_b,
               const float* __restrict__ w_u,
               const float* __restrict__ b_u,
               const float* __restrict__ b_st,
               const float* __restrict__ user_embedding,
               const float* __restrict__ user_emb_table,
               const float* __restrict__ theta,
               const int* __restrict__ user_id,
               int Bn, int N, int K, int BK, int hisBlocks, int nowBlocks)
{
    int tid  = threadIdx.x;
    int lane = tid & 31, warp = tid >> 5;

    if (blockIdx.x < (unsigned)hisBlocks) {
        __shared__ float w1s[128 * 64];     // 32 KB
        __shared__ float xs[8][2][128];     // 8 KB: two x rows per warp
        __shared__ float us[64];
        __shared__ float sh_bh2;

        // ---- stage all of w_his1 into registers (one DRAM round), hold while computing u ----
        float4 wreg[8];
        #pragma unroll
        for (int i = 0; i < 8; ++i)
            wreg[i] = reinterpret_cast<const float4*>(w_his1)[tid + i * 256];

        // ---- entry indices + x-row prefetch (also in flight) ----
        int e0 = blockIdx.x * 16 + warp * 2;
        int e1 = e0 + 1;
        bool v0 = e0 < BK, v1 = e1 < BK;
        int n0 = v0 ? his_nodes[e0] : 0;
        int n1 = v1 ? his_nodes[e1] : 0;
        float4 x0 = v0 ? reinterpret_cast<const float4*>(raw_field_embed + (size_t)n0 * 128)[lane]
                       : make_float4(0.f,0.f,0.f,0.f);
        float4 x1 = v1 ? reinterpret_cast<const float4*>(raw_field_embed + (size_t)n1 * 128)[lane]
                       : make_float4(0.f,0.f,0.f,0.f);

        // ---- u[j] = w_his2[j,:]·w_st : 8 warps x 8 rows, one round ----
        float4 wv = reinterpret_cast<const float4*>(w_st)[lane];
        {
            int r0 = warp * 8;
            float a[8];
            #pragma unroll
            for (int i = 0; i < 8; ++i) {
                float4 r = reinterpret_cast<const float4*>(w_his2 + (r0 + i) * 128)[lane];
                a[i] = r.x * wv.x + r.y * wv.y + r.z * wv.z + r.w * wv.w;
            }
            float d = reduce8(a, lane);
            int row = ((lane >> 4) & 1) * 4 + ((lane >> 3) & 1) * 2 + ((lane >> 2) & 1);
            if ((lane & 3) == 0) us[r0 + row] = d;
        }
        if (warp == 0) {
            float4 bh = reinterpret_cast<const float4*>(b_his2)[lane];
            float p = warp_sum(bh.x * wv.x + bh.y * wv.y + bh.z * wv.z + bh.w * wv.w);
            if (lane == 0) sh_bh2 = p;
        }

        // ---- commit staged weights + x rows to smem ----
        #pragma unroll
        for (int i = 0; i < 8; ++i)
            reinterpret_cast<float4*>(w1s)[tid + i * 256] = wreg[i];
        reinterpret_cast<float4*>(&xs[warp][0][0])[lane] = x0;
        reinterpret_cast<float4*>(&xs[warp][1][0])[lane] = x1;
        __syncthreads();

        // ---- dual-entry MLP: shared weight loads serve both entries ----
        float ba = b_his1[lane], bb = b_his1[lane + 32];
        float a0 = ba, a1 = bb;      // entry 0
        float c0 = ba, c1 = bb;      // entry 1
        const float* xp0 = &xs[warp][0][0];
        const float* xp1 = &xs[warp][1][0];
        #pragma unroll 8
        for (int d = 0; d < 128; ++d) {
            float w0 = w1s[d * 64 + lane];
            float w1 = w1s[d * 64 + lane + 32];
            float xa = xp0[d], xb = xp1[d];
            a0 += xa * w0; a1 += xa * w1;
            c0 += xb * w0; c1 += xb * w1;
        }
        float u0 = us[lane], u1 = us[lane + 32], bh2 = sh_bh2;
        float l;
        l = (a0 > 0.f ? a0 : 0.01f * a0) * u0 + (a1 > 0.f ? a1 : 0.01f * a1) * u1;
        float val0 = warp_sum(l);
        l = (c0 > 0.f ? c0 : 0.01f * c0) * u0 + (c1 > 0.f ? c1 : 0.01f * c1) * u1;
        float val1 = warp_sum(l);
        if (lane == 0 && v0) {
            int b = e0 / K;
            atomicAdd(&g_delta[(size_t)b * N + n0], alpha[n0] * (val0 + bh2));
            atomicOr(&g_flag[n0], 1u << b);
        }
        if (lane == 0 && v1) {
            int b = e1 / K;
            atomicAdd(&g_delta[(size_t)b * N + n1], alpha[n1] * (val1 + bh2));
            atomicOr(&g_flag[n1], 1u << b);
        }
    } else if (blockIdx.x < (unsigned)(hisBlocks + nowBlocks)) {
        // ---- now dot entries: prefetch 4 rows, then reduce ----
        int bb = blockIdx.x - hisBlocks;
        float4 w4 = reinterpret_cast<const float4*>(w_st)[lane];
        int   ns[4]; int bsv[4]; bool vv[4];
        float4 r[4];
        #pragma unroll
        for (int i = 0; i < 4; ++i) {
            int e = bb * 32 + warp * 4 + i;
            vv[i] = e < BK;
            ns[i] = vv[i] ? now_nodes[e] : 0;
            bsv[i] = vv[i] ? e / K : 0;
            r[i] = vv[i]
                 ? reinterpret_cast<const float4*>(station_embedding + (size_t)ns[i] * 128)[lane]
                 : make_float4(0.f,0.f,0.f,0.f);
        }
        #pragma unroll
        for (int i = 0; i < 4; ++i) {
            float p = warp_sum(r[i].x * w4.x + r[i].y * w4.y + r[i].z * w4.z + r[i].w * w4.w);
            if (lane == 0 && vv[i]) {
                atomicAdd(&g_delta[(size_t)bsv[i] * N + ns[i]], alpha[ns[i]] * p);
                atomicOr(&g_flag[ns[i]], 1u << bsv[i]);
            }
        }
    } else {
        // ---- prep: g_v (16 rows/warp, one round), g_U, g_c ----
        float4 wv = reinterpret_cast<const float4*>(w_st)[lane];
        {
            int r0 = warp * 16;
            float4 rr[16];
            #pragma unroll
            for (int i = 0; i < 16; ++i)
                rr[i] = reinterpret_cast<const float4*>(proj_w + (r0 + i) * 128)[lane];
            float a[8];
            #pragma unroll
            for (int i = 0; i < 8; ++i)
                a[i] = rr[i].x * wv.x + rr[i].y * wv.y + rr[i].z * wv.z + rr[i].w * wv.w;
            float d = reduce8(a, lane);
            int row = ((lane >> 4) & 1) * 4 + ((lane >> 3) & 1) * 2 + ((lane >> 2) & 1);
            if ((lane & 3) == 0) g_v[r0 + row] = d;
            #pragma unroll
            for (int i = 0; i < 8; ++i)
                a[i] = rr[i+8].x * wv.x + rr[i+8].y * wv.y + rr[i+8].z * wv.z + rr[i+8].w * wv.w;
            d = reduce8(a, lane);
            if ((lane & 3) == 0) g_v[r0 + 8 + row] = d;
        }
        int b = warp;
        if (b < Bn) {
            int uid = user_id[b];
            float th = theta[uid];
            float4 ue = reinterpret_cast<const float4*>(user_embedding + b * 128)[lane];
            float4 ut = reinterpret_cast<const float4*>(user_emb_table + (size_t)uid * 128)[lane];
            float4 wu = reinterpret_cast<const float4*>(w_u)[lane];
            float p = ((1.f - th) * ue.x + th * ut.x) * wu.x
                    + ((1.f - th) * ue.y + th * ut.y) * wu.y
                    + ((1.f - th) * ue.z + th * ut.z) * wu.z
                    + ((1.f - th) * ue.w + th * ut.w) * wu.w;
            p = warp_sum(p);
            if (lane == 0) g_U[b] = p + b_u[0] + b_st[0];
        }
        if (warp == 0) {
            float4 pb = reinterpret_cast<const float4*>(proj_b)[lane];
            float p = warp_sum(pb.x * wv.x + pb.y * wv.y + pb.z * wv.z + pb.w * wv.w);
            if (lane == 0) g_c = p;
        }
    }
}

// ---------------- K2: main sweep — EXACT R5 version (proven 11.4 us) ----------------
__global__ __launch_bounds__(256)
void main_kernel(const float* __restrict__ set_table,
                 const float* __restrict__ alpha,
                 float* __restrict__ out, int N, int Bn)
{
    __shared__ float    sh_s[64];
    __shared__ unsigned sh_f[64];
    __shared__ float    sh_U[16];
    int tid = threadIdx.x;
    int lane = tid & 31, warp = tid >> 5;
    int base = blockIdx.x * 64;

    if (tid < Bn) sh_U[tid] = g_U[tid];
    if (tid < 64) {
        int n = base + tid;
        sh_f[tid] = (n < N) ? g_flag[n] : 0u;
    }
    float4 v4 = reinterpret_cast<const float4*>(g_v)[lane];
    float cval = g_c;

    int n0 = base + warp * 8;
    float4 r[8];
    #pragma unroll
    for (int i = 0; i < 8; ++i) {
        int n = n0 + i;
        r[i] = (n < N)
             ? reinterpret_cast<const float4*>(set_table + (size_t)n * 128)[lane]
             : make_float4(0.f, 0.f, 0.f, 0.f);
    }
    #pragma unroll
    for (int i = 0; i < 8; ++i) {
        float p = warp_sum(r[i].x * v4.x + r[i].y * v4.y + r[i].z * v4.z + r[i].w * v4.w);
        if (lane == 0)
            sh_s[warp * 8 + i] = p + cval;
    }
    __syncthreads();

    int count = N - base; if (count > 64) count = 64;
    #pragma unroll
    for (int idx = tid; idx < Bn * 64; idx += 256) {
        int b = idx >> 6, j = idx & 63;
        if (j < count) {
            int n = base + j;
            float s = sh_s[j];
            float val = s + sh_U[b];
            unsigned f = sh_f[j];
            if (f) {
                if ((f >> b) & 1u) {
                    val = (1.f - alpha[n]) * s + sh_U[b] + g_delta[(size_t)b * N + n];
                    g_delta[(size_t)b * N + n] = 0.f;   // restore zero for next replay
                }
                if (b == 0) g_flag[n] = 0u;             // restore zero for next replay
            }
            out[(size_t)b * N + n] = val;
        }
    }
}

// ---------------- host launch ----------------
extern "C" void kernel_launch(void* const* d_in, const int* in_sizes, int n_in,
                              void* d_out, int out_size)
{
    int iUE, iSE, iRFE, iHIS, iNOW, iUID, iUET, iSET, iPW, iPB, iTH, iAL,
        iW1, iB1, iW2, iB2, iWST, iBST, iWU, iBU;
    if (in_sizes[3] < 100000) {
        iUE=0; iSE=1; iRFE=2; iHIS=3; iNOW=4; iUID=5; iUET=6; iSET=7; iPW=8; iPB=9;
        iTH=10; iAL=11; iW1=12; iB1=13; iW2=14; iB2=15; iWST=16; iBST=17; iWU=18; iBU=19;
    } else {
        iUE=0; iSE=1; iRFE=2; iUET=3; iSET=4; iPW=5; iPB=6; iTH=7; iAL=8; iW1=9;
        iB1=10; iW2=11; iB2=12; iWST=13; iBST=14; iWU=15; iBU=16; iHIS=17; iNOW=18; iUID=19;
    }

    const float* user_embedding    = (const float*)d_in[iUE];
    const float* station_embedding = (const float*)d_in[iSE];
    const float* raw_field_embed   = (const float*)d_in[iRFE];
    const float* user_emb_table    = (const float*)d_in[iUET];
    const float* station_emb_table = (const float*)d_in[iSET];
    const float* proj_w            = (const float*)d_in[iPW];
    const float* proj_b            = (const float*)d_in[iPB];
    const float* theta             = (const float*)d_in[iTH];
    const float* alpha             = (const float*)d_in[iAL];
    const float* w_his1            = (const float*)d_in[iW1];
    const float* b_his1            = (const float*)d_in[iB1];
    const float* w_his2            = (const float*)d_in[iW2];
    const float* b_his2            = (const float*)d_in[iB2];
    const float* w_st              = (const float*)d_in[iWST];
    const float* b_st              = (const float*)d_in[iBST];
    const float* w_u               = (const float*)d_in[iWU];
    const float* b_u               = (const float*)d_in[iBU];
    const int*   his_nodes         = (const int*)d_in[iHIS];
    const int*   now_nodes         = (const int*)d_in[iNOW];
    const int*   user_id           = (const int*)d_in[iUID];

    int B  = in_sizes[iUE] / 128;     // 8
    int N  = in_sizes[iAL];           // 60082
    int BK = in_sizes[iHIS];          // 256
    int K  = BK / B;                  // 32

    float* out = (float*)d_out;
    (void)out_size; (void)n_in;

    int hisBlocks = (BK + 15) / 16;   // 16 blocks, 2 entries/warp
    int nowBlocks = (BK + 31) / 32;   // 8 blocks
    k1_kernel<<<hisBlocks + nowBlocks + 1, 256>>>(
        now_nodes, his_nodes, alpha, station_embedding, raw_field_embed,
        w_st, w_his1, b_his1, w_his2, b_his2, proj_w, proj_b,
        w_u, b_u, b_st, user_embedding, user_emb_table, theta, user_id,
        B, N, K, BK, hisBlocks, nowBlocks);

    int grid = (N + 63) / 64;
    main_kernel<<<grid, 256>>>(station_emb_table, alpha, out, N, B);
}